// round 16
// baseline (speedup 1.0000x reference)
#include <cuda_runtime.h>
#include <stdint.h>

// Problem constants: L=16 (hardcoded), B<=128, inner vector = 8*2*2*2 = 64.
#define MAXB 128

// Static device scratch (no cudaMalloc anywhere).
__device__ unsigned char g_code[MAXB * 4096];   // per-cell (nz<<6)|c byte
__device__ float g_partial[MAXB * 64 * 128];    // per-(batch,task) [bank0|bank1]
__device__ int g_ticket[MAXB];                  // arrivals; reset by setup

// Phi: phi=[0,3,2,1,6,5,4,7] on both 3-bit halves. XOR-linear involution:
// bit0'=b0, bit2'=b2, bit1'=parity of the half.
__device__ __forceinline__ unsigned PHI(unsigned u) {
    return (u & 0x2Du)
         | ((unsigned)(__popc(u & 7u) & 1) << 1)
         | ((unsigned)(__popc((u >> 3) & 7u) & 1) << 4);
}

// flags[0] = parity(all); flags[m>=1] = parity(g[0] + g[15]+...+g[17-m])
__device__ __forceinline__ void flagrow(const unsigned* g, unsigned* f) {
    unsigned tot = 0;
#pragma unroll
    for (int m = 0; m < 16; ++m) tot ^= g[m];
    f[0] = tot & 1u;
    unsigned acc = g[0] & 1u;
    f[1] = acc;
#pragma unroll
    for (int m = 2; m < 16; ++m) { acc ^= g[17 - m] & 1u; f[m] = acc; }
}

// Streaming (evict-first) float4 load / store — x is touched exactly once.
__device__ __forceinline__ float4 ldcs4(const float4* p) {
    float4 v;
    asm volatile("ld.global.cs.v4.f32 {%0,%1,%2,%3}, [%4];"
                 : "=f"(v.x), "=f"(v.y), "=f"(v.z), "=f"(v.w) : "l"(p));
    return v;
}
__device__ __forceinline__ void stcs4(float4* p, float4 v) {
    asm volatile("st.global.cs.v4.f32 [%0], {%1,%2,%3,%4};"
                 :: "l"(p), "f"(v.x), "f"(v.y), "f"(v.z), "f"(v.w) : "memory");
}

// ---------------------------------------------------------------------------
// Kernel 1: per-batch flag parities + per-cell affine code byte.
// NEW: prefetches this batch's 1 MB of x into L2 at kernel entry, so the
// x-stream occupies the (otherwise idle) DRAM bus for setup's whole duration
// — widening the PDL overlap window from the producer side.
// Ends with griddepcontrol.launch_dependents.
// ---------------------------------------------------------------------------
__global__ __launch_bounds__(1024) void setup_kernel(const int* __restrict__ syn,
                                                     const float* __restrict__ x) {
    const int b = blockIdx.x;
    const int tid = threadIdx.x;
    const int group = tid >> 8;    // channel 0..3 (z, x0, x1, x2)
    const int gt = tid & 255;
    const int* row = syn + (size_t)b * 16384;

    // --- Entry: prefetch batch b's x region (4096 cells = 1 MB) into L2 ---
    {
        const char* p = reinterpret_cast<const char*>(x)
                      + (size_t)b * 4096 * 256 + (size_t)tid * 128;
#pragma unroll
        for (int i = 0; i < 8; ++i)
            asm volatile("prefetch.global.L2 [%0];" :: "l"(p + (size_t)i * 131072));
    }

    if (tid == 0) g_ticket[b] = 0;   // reset pool ticket each launch

    __shared__ unsigned zb[256];
    __shared__ unsigned surf0[256], surf1[256], surf2[256];
    __shared__ unsigned t1[256], t2[256];
    __shared__ unsigned xw[8];
    __shared__ unsigned sx[3][16];
    __shared__ unsigned fz0[256], fz1[256], fz2[256];
    __shared__ unsigned fxs[3][16];

    // Phase 1: each group loads its channel, thread = (d1,d2), 16 ints over d3.
    {
        const int4* p = reinterpret_cast<const int4*>(row + 4096 * group) + gt * 4;
        unsigned m = 0;
#pragma unroll
        for (int v = 0; v < 4; ++v) {
            int4 w = p[v];
            m |= (unsigned)(w.x & 1) << (v * 4 + 0);
            m |= (unsigned)(w.y & 1) << (v * 4 + 1);
            m |= (unsigned)(w.z & 1) << (v * 4 + 2);
            m |= (unsigned)(w.w & 1) << (v * 4 + 3);
        }
        if (group == 0) {
            zb[gt] = m;
        } else if (group == 1) {
            unsigned r = m;
#pragma unroll
            for (int off = 16; off > 0; off >>= 1)
                r ^= __shfl_xor_sync(0xffffffffu, r, off);
            if ((tid & 31) == 0) xw[(gt >> 5)] = r;
        } else if (group == 2) {
            t1[gt] = (unsigned)(__popc(m) & 1);
        } else {
            t2[gt] = (unsigned)(__popc(m) & 1);
        }
    }
    __syncthreads();

    // Phase 2: surfaces & x line parities (work spread over groups).
    if (group == 0) {
        const int hi = gt >> 4, lo = gt & 15;
        unsigned a = 0;
#pragma unroll
        for (int d = 0; d < 16; ++d)
            a ^= (zb[d * 16 + hi] >> lo) & 1u;  // surf0[d2=hi][d3=lo]
        surf0[gt] = a;
        surf2[gt] = (unsigned)(__popc(zb[gt]) & 1);
    } else if (group == 3) {
        const int hi = gt >> 4, lo = gt & 15;
        unsigned c = 0;
#pragma unroll
        for (int d = 0; d < 16; ++d)
            c ^= (zb[hi * 16 + d] >> lo) & 1u;  // surf1[d1=hi][d3=lo]
        surf1[gt] = c;
        if (gt < 16) {
            unsigned a = 0;
#pragma unroll
            for (int d1 = 0; d1 < 16; ++d1) a ^= t2[d1 * 16 + gt];
            sx[2][gt] = a;                                 // sx2[d2]
        }
    } else if (group == 1 && gt < 16) {
        unsigned w = 0;
#pragma unroll
        for (int i = 0; i < 8; ++i) w ^= xw[i];
        sx[0][gt] = (w >> gt) & 1u;                        // sx0[d3]
    } else if (group == 2 && gt < 16) {
        unsigned a = 0;
#pragma unroll
        for (int d2 = 0; d2 < 16; ++d2) a ^= t1[gt * 16 + d2];
        sx[1][gt] = a;                                     // sx1[d1]
    }
    __syncthreads();

    // Phase 3: flags.
    if (tid < 48) {
        const int which = tid >> 4;
        const int p = tid & 15;
        const unsigned* g = (which == 0) ? &surf0[p * 16]
                          : (which == 1) ? &surf1[p * 16] : &surf2[p * 16];
        unsigned* f = (which == 0) ? &fz0[p * 16]
                    : (which == 1) ? &fz1[p * 16] : &fz2[p * 16];
        flagrow(g, f);
    } else if (tid < 51) {
        const int ch = tid - 48;
        unsigned g[16];
#pragma unroll
        for (int m = 0; m < 16; ++m)
            g[m] = (ch == 0) ? sx[0][(m - 1) & 15] : sx[ch][m];  // x0 shift=1
        flagrow(g, fxs[ch]);
    }
    __syncthreads();

    // Phase 4: per-cell code bytes. Pi(q) = Phi^nz(q) ^ c, eval X2,Z2,X1,Z1,X0,Z0.
    for (int idx = tid; idx < 4096; idx += 1024) {
        const int I = idx >> 8, J = (idx >> 4) & 15, K = idx & 15;
        const unsigned z0 = fz0[K * 16 + J], x0f = fxs[0][K];
        const unsigned z1 = fz1[I * 16 + K], x1f = fxs[1][I];
        const unsigned z2 = fz2[J * 16 + I], x2f = fxs[2][J];
        unsigned t = 0;
        if (x2f) t ^= 4u;
        if (z2)  t = PHI(t) ^ 8u;
        if (x1f) t ^= 2u;
        if (z1)  t = PHI(t) ^ 16u;
        if (x0f) t ^= 1u;
        if (z0)  t = PHI(t) ^ 32u;
        const unsigned nz = (z0 ^ z1 ^ z2) & 1u;
        g_code[(size_t)b * 4096 + idx] = (unsigned char)(t | (nz << 6));
    }

    // Signal dependent (PDL): codes for this CTA's batch are written.
    __threadfence();
    asm volatile("griddepcontrol.launch_dependents;" ::: "memory");
}

// ---------------------------------------------------------------------------
// Kernel 2 (hot): R15 hybrid, byte-identical (measured best).
//   Pre-wait:  L2 prefetch of the CTA's 128 KB region + code-INDEPENDENT
//              loads of words 0-1 (own-quad addressing).
//   Post-wait: words 0-1 consumed via shfl-permute (16 shfl/warp);
//              words 2-15 code-addressed loads + FSEL consume, interleaved
//              double-buffered bursts.
// ---------------------------------------------------------------------------
__global__ __launch_bounds__(256, 3) void pool_kernel(const float* __restrict__ x,
                                                      float* __restrict__ out) {
    const int b    = blockIdx.x >> 3;
    const int rc   = blockIdx.x & 7;
    const int wb   = (rc << 3) | (threadIdx.x >> 5);  // 0..63
    const int lane = threadIdx.x & 31;
    const int t    = lane & 15;
    const int h    = lane >> 4;
    const int cell0 = wb * 64;

    // --- Pre-wait: prefetch CTA's x region (512 cells = 128 KB) into L2 ---
    {
        const char* p = reinterpret_cast<const char*>(x)
                      + ((size_t)b * 4096 + (size_t)rc * 512) * 256
                      + (size_t)threadIdx.x * 128;
#pragma unroll
        for (int i = 0; i < 4; ++i)
            asm volatile("prefetch.global.L2 [%0];" :: "l"(p + (size_t)i * 32768));
    }

    const float4* __restrict__ xb =
        reinterpret_cast<const float4*>(x + ((size_t)b * 4096 + cell0) * 64);
    const unsigned* __restrict__ cb =
        reinterpret_cast<const unsigned*>(g_code + (size_t)b * 4096 + cell0);
    const int sh0 = h * 8;
    const int qoff = 16 * h + t;   // lane's own quad within a cell

    // Pre-wait: code-independent loads of words 0-1 (4 loads/lane).
    float4 pre[4];
#pragma unroll
    for (int w = 0; w < 2; ++w)
#pragma unroll
        for (int j = 0; j < 2; ++j)
            pre[w * 2 + j] = ldcs4(xb + (size_t)w * 64 + j * 32 + qoff);

    // Gate code-dependent work on setup completion.
    asm volatile("griddepcontrol.wait;" ::: "memory");
    const unsigned packed = cb[lane & 15];   // 16 words = this warp's 64 codes

    float a0 = 0.f, a1 = 0.f, a2 = 0.f, a3 = 0.f;   // bank0, quad t
    float b0 = 0.f, b1 = 0.f, b2 = 0.f, b3 = 0.f;   // bank1, quad t

#define ACCUM(code, vv)                                                        \
    do {                                                                       \
        const bool s1 = ((code) & 1u) != 0u;                                   \
        const bool s2 = ((code) & 2u) != 0u;                                   \
        const float e0 = s1 ? (vv).y : (vv).x;                                 \
        const float e1 = s1 ? (vv).x : (vv).y;                                 \
        const float e2 = s1 ? (vv).w : (vv).z;                                 \
        const float e3 = s1 ? (vv).z : (vv).w;                                 \
        const float f0 = s2 ? e2 : e0;                                         \
        const float f1 = s2 ? e3 : e1;                                         \
        const float f2 = s2 ? e0 : e2;                                         \
        const float f3 = s2 ? e1 : e3;                                         \
        if ((code) & 64u) { b0 += f0; b1 += f1; b2 += f2; b3 += f3; }          \
        else              { a0 += f0; a1 += f1; a2 += f2; a3 += f3; }          \
    } while (0)

#define LOADB(w0, n, cd, buf)                                                  \
    do {                                                                       \
        _Pragma("unroll")                                                      \
        for (int k = 0; k < (n); ++k) {                                        \
            const unsigned pk = __shfl_sync(0xffffffffu, packed, (w0) + k);    \
            _Pragma("unroll")                                                  \
            for (int j = 0; j < 2; ++j) {                                      \
                const unsigned code = (pk >> (sh0 + j * 16)) & 0xffu;          \
                (cd)[k * 2 + j] = code;                                        \
                (buf)[k * 2 + j] =                                             \
                    ldcs4(xb + (size_t)((w0) + k) * 64 + j * 32 + 16 * h       \
                          + (t ^ (int)((code >> 2) & 15u)));                   \
            }                                                                  \
        }                                                                      \
    } while (0)

#define CONSB(n, cd, buf)                                                      \
    do {                                                                       \
        _Pragma("unroll")                                                      \
        for (int i = 0; i < 2 * (n); ++i) ACCUM((cd)[i], (buf)[i]);            \
    } while (0)

    unsigned cdA[8]; float4 bufA[8];
    unsigned cdB[8]; float4 bufB[8];

    // Burst A (words 2-5) issued first so its loads fly while we consume pre.
    LOADB(2, 4, cdA, bufA);

    // Consume pre-loaded words 0-1 via shfl-permute (quad t -> t^(c>>2)).
#pragma unroll
    for (int w = 0; w < 2; ++w) {
        const unsigned pk = __shfl_sync(0xffffffffu, packed, w);
#pragma unroll
        for (int j = 0; j < 2; ++j) {
            const unsigned code = (pk >> (sh0 + j * 16)) & 0xffu;
            const int lm = (int)((code >> 2) & 15u);
            const float4 v = pre[w * 2 + j];
            float4 ww;
            ww.x = __shfl_xor_sync(0xffffffffu, v.x, lm, 16);
            ww.y = __shfl_xor_sync(0xffffffffu, v.y, lm, 16);
            ww.z = __shfl_xor_sync(0xffffffffu, v.z, lm, 16);
            ww.w = __shfl_xor_sync(0xffffffffu, v.w, lm, 16);
            ACCUM(code, ww);
        }
    }

    LOADB(6, 4, cdB, bufB);    // words 6-9 in flight
    CONSB(4, cdA, bufA);
    LOADB(10, 4, cdA, bufA);   // words 10-13 in flight
    CONSB(4, cdB, bufB);
    LOADB(14, 2, cdB, bufB);   // words 14-15 in flight
    CONSB(4, cdA, bufA);
    CONSB(2, cdB, bufB);

#undef ACCUM
#undef LOADB
#undef CONSB

    // Combine half-warps (lanes l and l^16 hold the same quad t).
    a0 += __shfl_xor_sync(0xffffffffu, a0, 16);
    a1 += __shfl_xor_sync(0xffffffffu, a1, 16);
    a2 += __shfl_xor_sync(0xffffffffu, a2, 16);
    a3 += __shfl_xor_sync(0xffffffffu, a3, 16);
    b0 += __shfl_xor_sync(0xffffffffu, b0, 16);
    b1 += __shfl_xor_sync(0xffffffffu, b1, 16);
    b2 += __shfl_xor_sync(0xffffffffu, b2, 16);
    b3 += __shfl_xor_sync(0xffffffffu, b3, 16);

    float* dst = g_partial + ((size_t)b * 64 + wb) * 128;
    const float4 r = (h == 0) ? make_float4(a0, a1, a2, a3)
                              : make_float4(b0, b1, b2, b3);
    stcs4(reinterpret_cast<float4*>(dst) + h * 16 + t, r);  // [bank0|bank1]

    // --- last-CTA-per-batch reduction (8 CTAs per batch) ---
    __shared__ int s_last;
    __threadfence();
    __syncthreads();
    if (threadIdx.x == 0) {
        const int v = atomicAdd(&g_ticket[b], 1);
        s_last = (v == 7) ? 1 : 0;
    }
    __syncthreads();
    if (!s_last) return;
    __threadfence();

    const float* __restrict__ prt = g_partial + (size_t)b * 8192;  // 64 x 128
    const int col  = threadIdx.x & 127;
    const int half = threadIdx.x >> 7;
    float s = 0.f;
#pragma unroll
    for (int r2 = 0; r2 < 32; ++r2)
        s += prt[(half * 32 + r2) * 128 + col];
    __shared__ float sb[256];
    sb[half * 128 + col] = s;
    __syncthreads();
    if (threadIdx.x < 64) {
        const int q = threadIdx.x;
        const int qp = (int)PHI((unsigned)q);
        const float s0 = sb[q] + sb[128 + q];
        const float s1v = sb[64 + qp] + sb[192 + qp];
        out[b * 64 + q] = (s0 + s1v) * (1.0f / 4096.0f);
    }
}

extern "C" void kernel_launch(void* const* d_in, const int* in_sizes, int n_in,
                              void* d_out, int out_size) {
    const float* x;
    const int* syn;
    if (in_sizes[0] >= in_sizes[1]) {
        x = (const float*)d_in[0];
        syn = (const int*)d_in[1];
    } else {
        x = (const float*)d_in[1];
        syn = (const int*)d_in[0];
    }
    int B;
    {
        int xs = (in_sizes[0] >= in_sizes[1]) ? in_sizes[0] : in_sizes[1];
        B = xs / (4096 * 64);
        if (B > MAXB) B = MAXB;
    }

    setup_kernel<<<B, 1024>>>(syn, x);

    // PDL: pool CTAs start while setup drains; prefetch + words 0-1 are
    // code-independent, so only the code-addressed bulk waits on setup.
    cudaLaunchConfig_t cfg = {};
    cfg.gridDim  = dim3((unsigned)(B * 8));
    cfg.blockDim = dim3(256);
    cfg.dynamicSmemBytes = 0;
    cfg.stream = 0;
    cudaLaunchAttribute attrs[1];
    attrs[0].id = cudaLaunchAttributeProgrammaticStreamSerialization;
    attrs[0].val.programmaticStreamSerializationAllowed = 1;
    cfg.attrs = attrs;
    cfg.numAttrs = 1;
    cudaLaunchKernelEx(&cfg, pool_kernel, x, (float*)d_out);
}

// round 17
// speedup vs baseline: 1.1404x; 1.1404x over previous
#include <cuda_runtime.h>
#include <stdint.h>

// Problem constants: L=16 (hardcoded), B<=128, inner vector = 8*2*2*2 = 64.
#define MAXB 128

// Static device scratch (no cudaMalloc anywhere).
__device__ unsigned char g_code[MAXB * 4096];   // per-cell (nz<<6)|c byte
__device__ float g_partial[MAXB * 64 * 128];    // per-(batch,task) [bank0|bank1]
__device__ int g_ticket[MAXB];                  // arrivals; reset by setup

// Phi: phi=[0,3,2,1,6,5,4,7] on both 3-bit halves. XOR-linear involution:
// bit0'=b0, bit2'=b2, bit1'=parity of the half.
__device__ __forceinline__ unsigned PHI(unsigned u) {
    return (u & 0x2Du)
         | ((unsigned)(__popc(u & 7u) & 1) << 1)
         | ((unsigned)(__popc((u >> 3) & 7u) & 1) << 4);
}

// flags[0] = parity(all); flags[m>=1] = parity(g[0] + g[15]+...+g[17-m])
__device__ __forceinline__ void flagrow(const unsigned* g, unsigned* f) {
    unsigned tot = 0;
#pragma unroll
    for (int m = 0; m < 16; ++m) tot ^= g[m];
    f[0] = tot & 1u;
    unsigned acc = g[0] & 1u;
    f[1] = acc;
#pragma unroll
    for (int m = 2; m < 16; ++m) { acc ^= g[17 - m] & 1u; f[m] = acc; }
}

// Streaming (evict-first) float4 load / store — x is touched exactly once.
__device__ __forceinline__ float4 ldcs4(const float4* p) {
    float4 v;
    asm volatile("ld.global.cs.v4.f32 {%0,%1,%2,%3}, [%4];"
                 : "=f"(v.x), "=f"(v.y), "=f"(v.z), "=f"(v.w) : "l"(p));
    return v;
}
__device__ __forceinline__ void stcs4(float4* p, float4 v) {
    asm volatile("st.global.cs.v4.f32 [%0], {%1,%2,%3,%4};"
                 :: "l"(p), "f"(v.x), "f"(v.y), "f"(v.z), "f"(v.w) : "memory");
}

// ---------------------------------------------------------------------------
// Kernel 1: per-batch flag parities + per-cell affine code byte. R15 version
// (NO x prefetch — R16 proved producer-side prefetch delays the PDL signal).
// Ends with griddepcontrol.launch_dependents.
// ---------------------------------------------------------------------------
__global__ __launch_bounds__(1024) void setup_kernel(const int* __restrict__ syn) {
    const int b = blockIdx.x;
    const int tid = threadIdx.x;
    const int group = tid >> 8;    // channel 0..3 (z, x0, x1, x2)
    const int gt = tid & 255;
    const int* row = syn + (size_t)b * 16384;

    if (tid == 0) g_ticket[b] = 0;   // reset pool ticket each launch

    __shared__ unsigned zb[256];
    __shared__ unsigned surf0[256], surf1[256], surf2[256];
    __shared__ unsigned t1[256], t2[256];
    __shared__ unsigned xw[8];
    __shared__ unsigned sx[3][16];
    __shared__ unsigned fz0[256], fz1[256], fz2[256];
    __shared__ unsigned fxs[3][16];

    // Phase 1: each group loads its channel, thread = (d1,d2), 16 ints over d3.
    {
        const int4* p = reinterpret_cast<const int4*>(row + 4096 * group) + gt * 4;
        unsigned m = 0;
#pragma unroll
        for (int v = 0; v < 4; ++v) {
            int4 w = p[v];
            m |= (unsigned)(w.x & 1) << (v * 4 + 0);
            m |= (unsigned)(w.y & 1) << (v * 4 + 1);
            m |= (unsigned)(w.z & 1) << (v * 4 + 2);
            m |= (unsigned)(w.w & 1) << (v * 4 + 3);
        }
        if (group == 0) {
            zb[gt] = m;
        } else if (group == 1) {
            unsigned r = m;
#pragma unroll
            for (int off = 16; off > 0; off >>= 1)
                r ^= __shfl_xor_sync(0xffffffffu, r, off);
            if ((tid & 31) == 0) xw[(gt >> 5)] = r;
        } else if (group == 2) {
            t1[gt] = (unsigned)(__popc(m) & 1);
        } else {
            t2[gt] = (unsigned)(__popc(m) & 1);
        }
    }
    __syncthreads();

    // Phase 2: surfaces & x line parities (work spread over groups).
    if (group == 0) {
        const int hi = gt >> 4, lo = gt & 15;
        unsigned a = 0;
#pragma unroll
        for (int d = 0; d < 16; ++d)
            a ^= (zb[d * 16 + hi] >> lo) & 1u;  // surf0[d2=hi][d3=lo]
        surf0[gt] = a;
        surf2[gt] = (unsigned)(__popc(zb[gt]) & 1);
    } else if (group == 3) {
        const int hi = gt >> 4, lo = gt & 15;
        unsigned c = 0;
#pragma unroll
        for (int d = 0; d < 16; ++d)
            c ^= (zb[hi * 16 + d] >> lo) & 1u;  // surf1[d1=hi][d3=lo]
        surf1[gt] = c;
        if (gt < 16) {
            unsigned a = 0;
#pragma unroll
            for (int d1 = 0; d1 < 16; ++d1) a ^= t2[d1 * 16 + gt];
            sx[2][gt] = a;                                 // sx2[d2]
        }
    } else if (group == 1 && gt < 16) {
        unsigned w = 0;
#pragma unroll
        for (int i = 0; i < 8; ++i) w ^= xw[i];
        sx[0][gt] = (w >> gt) & 1u;                        // sx0[d3]
    } else if (group == 2 && gt < 16) {
        unsigned a = 0;
#pragma unroll
        for (int d2 = 0; d2 < 16; ++d2) a ^= t1[gt * 16 + d2];
        sx[1][gt] = a;                                     // sx1[d1]
    }
    __syncthreads();

    // Phase 3: flags.
    if (tid < 48) {
        const int which = tid >> 4;
        const int p = tid & 15;
        const unsigned* g = (which == 0) ? &surf0[p * 16]
                          : (which == 1) ? &surf1[p * 16] : &surf2[p * 16];
        unsigned* f = (which == 0) ? &fz0[p * 16]
                    : (which == 1) ? &fz1[p * 16] : &fz2[p * 16];
        flagrow(g, f);
    } else if (tid < 51) {
        const int ch = tid - 48;
        unsigned g[16];
#pragma unroll
        for (int m = 0; m < 16; ++m)
            g[m] = (ch == 0) ? sx[0][(m - 1) & 15] : sx[ch][m];  // x0 shift=1
        flagrow(g, fxs[ch]);
    }
    __syncthreads();

    // Phase 4: per-cell code bytes. Pi(q) = Phi^nz(q) ^ c, eval X2,Z2,X1,Z1,X0,Z0.
    for (int idx = tid; idx < 4096; idx += 1024) {
        const int I = idx >> 8, J = (idx >> 4) & 15, K = idx & 15;
        const unsigned z0 = fz0[K * 16 + J], x0f = fxs[0][K];
        const unsigned z1 = fz1[I * 16 + K], x1f = fxs[1][I];
        const unsigned z2 = fz2[J * 16 + I], x2f = fxs[2][J];
        unsigned t = 0;
        if (x2f) t ^= 4u;
        if (z2)  t = PHI(t) ^ 8u;
        if (x1f) t ^= 2u;
        if (z1)  t = PHI(t) ^ 16u;
        if (x0f) t ^= 1u;
        if (z0)  t = PHI(t) ^ 32u;
        const unsigned nz = (z0 ^ z1 ^ z2) & 1u;
        g_code[(size_t)b * 4096 + idx] = (unsigned char)(t | (nz << 6));
    }

    // Signal dependent (PDL): codes for this CTA's batch are written.
    __threadfence();
    asm volatile("griddepcontrol.launch_dependents;" ::: "memory");
}

// ---------------------------------------------------------------------------
// Kernel 2 (hot): R15 hybrid with WIDENED pre-wait window.
//   Pre-wait:  L2 prefetch of the CTA's 128 KB region + code-INDEPENDENT
//              loads of words 0-3 (own-quad addressing, 8 ldcs4/lane).
//   Post-wait: words 0-3 consumed via shfl-permute (32 shfl/warp);
//              words 4-15 code-addressed loads + FSEL consume, interleaved
//              double-buffered 4-word bursts.
// __launch_bounds__(256,3): 85-reg budget (peak pre[8]+bufA[8] = 64 buf regs,
// same as R15's measured bufA+bufB peak).
// ---------------------------------------------------------------------------
__global__ __launch_bounds__(256, 3) void pool_kernel(const float* __restrict__ x,
                                                      float* __restrict__ out) {
    const int b    = blockIdx.x >> 3;
    const int rc   = blockIdx.x & 7;
    const int wb   = (rc << 3) | (threadIdx.x >> 5);  // 0..63
    const int lane = threadIdx.x & 31;
    const int t    = lane & 15;
    const int h    = lane >> 4;
    const int cell0 = wb * 64;

    // --- Pre-wait: prefetch CTA's x region (512 cells = 128 KB) into L2 ---
    {
        const char* p = reinterpret_cast<const char*>(x)
                      + ((size_t)b * 4096 + (size_t)rc * 512) * 256
                      + (size_t)threadIdx.x * 128;
#pragma unroll
        for (int i = 0; i < 4; ++i)
            asm volatile("prefetch.global.L2 [%0];" :: "l"(p + (size_t)i * 32768));
    }

    const float4* __restrict__ xb =
        reinterpret_cast<const float4*>(x + ((size_t)b * 4096 + cell0) * 64);
    const unsigned* __restrict__ cb =
        reinterpret_cast<const unsigned*>(g_code + (size_t)b * 4096 + cell0);
    const int sh0 = h * 8;
    const int qoff = 16 * h + t;   // lane's own quad within a cell

    // Pre-wait: code-independent loads of words 0-3 (8 loads/lane).
    float4 pre[8];
#pragma unroll
    for (int w = 0; w < 4; ++w)
#pragma unroll
        for (int j = 0; j < 2; ++j)
            pre[w * 2 + j] = ldcs4(xb + (size_t)w * 64 + j * 32 + qoff);

    // Gate code-dependent work on setup completion.
    asm volatile("griddepcontrol.wait;" ::: "memory");
    const unsigned packed = cb[lane & 15];   // 16 words = this warp's 64 codes

    float a0 = 0.f, a1 = 0.f, a2 = 0.f, a3 = 0.f;   // bank0, quad t
    float b0 = 0.f, b1 = 0.f, b2 = 0.f, b3 = 0.f;   // bank1, quad t

#define ACCUM(code, vv)                                                        \
    do {                                                                       \
        const bool s1 = ((code) & 1u) != 0u;                                   \
        const bool s2 = ((code) & 2u) != 0u;                                   \
        const float e0 = s1 ? (vv).y : (vv).x;                                 \
        const float e1 = s1 ? (vv).x : (vv).y;                                 \
        const float e2 = s1 ? (vv).w : (vv).z;                                 \
        const float e3 = s1 ? (vv).z : (vv).w;                                 \
        const float f0 = s2 ? e2 : e0;                                         \
        const float f1 = s2 ? e3 : e1;                                         \
        const float f2 = s2 ? e0 : e2;                                         \
        const float f3 = s2 ? e1 : e3;                                         \
        if ((code) & 64u) { b0 += f0; b1 += f1; b2 += f2; b3 += f3; }          \
        else              { a0 += f0; a1 += f1; a2 += f2; a3 += f3; }          \
    } while (0)

#define LOADB(w0, n, cd, buf)                                                  \
    do {                                                                       \
        _Pragma("unroll")                                                      \
        for (int k = 0; k < (n); ++k) {                                        \
            const unsigned pk = __shfl_sync(0xffffffffu, packed, (w0) + k);    \
            _Pragma("unroll")                                                  \
            for (int j = 0; j < 2; ++j) {                                      \
                const unsigned code = (pk >> (sh0 + j * 16)) & 0xffu;          \
                (cd)[k * 2 + j] = code;                                        \
                (buf)[k * 2 + j] =                                             \
                    ldcs4(xb + (size_t)((w0) + k) * 64 + j * 32 + 16 * h       \
                          + (t ^ (int)((code >> 2) & 15u)));                   \
            }                                                                  \
        }                                                                      \
    } while (0)

#define CONSB(n, cd, buf)                                                      \
    do {                                                                       \
        _Pragma("unroll")                                                      \
        for (int i = 0; i < 2 * (n); ++i) ACCUM((cd)[i], (buf)[i]);            \
    } while (0)

    unsigned cdA[8]; float4 bufA[8];
    unsigned cdB[8]; float4 bufB[8];

    // Burst A (words 4-7) issued first so its loads fly while we consume pre.
    LOADB(4, 4, cdA, bufA);

    // Consume pre-loaded words 0-3 via shfl-permute (quad t -> t^(c>>2)).
#pragma unroll
    for (int w = 0; w < 4; ++w) {
        const unsigned pk = __shfl_sync(0xffffffffu, packed, w);
#pragma unroll
        for (int j = 0; j < 2; ++j) {
            const unsigned code = (pk >> (sh0 + j * 16)) & 0xffu;
            const int lm = (int)((code >> 2) & 15u);
            const float4 v = pre[w * 2 + j];
            float4 ww;
            ww.x = __shfl_xor_sync(0xffffffffu, v.x, lm, 16);
            ww.y = __shfl_xor_sync(0xffffffffu, v.y, lm, 16);
            ww.z = __shfl_xor_sync(0xffffffffu, v.z, lm, 16);
            ww.w = __shfl_xor_sync(0xffffffffu, v.w, lm, 16);
            ACCUM(code, ww);
        }
    }

    LOADB(8, 4, cdB, bufB);    // words 8-11 in flight
    CONSB(4, cdA, bufA);
    LOADB(12, 4, cdA, bufA);   // words 12-15 in flight
    CONSB(4, cdB, bufB);
    CONSB(4, cdA, bufA);

#undef ACCUM
#undef LOADB
#undef CONSB

    // Combine half-warps (lanes l and l^16 hold the same quad t).
    a0 += __shfl_xor_sync(0xffffffffu, a0, 16);
    a1 += __shfl_xor_sync(0xffffffffu, a1, 16);
    a2 += __shfl_xor_sync(0xffffffffu, a2, 16);
    a3 += __shfl_xor_sync(0xffffffffu, a3, 16);
    b0 += __shfl_xor_sync(0xffffffffu, b0, 16);
    b1 += __shfl_xor_sync(0xffffffffu, b1, 16);
    b2 += __shfl_xor_sync(0xffffffffu, b2, 16);
    b3 += __shfl_xor_sync(0xffffffffu, b3, 16);

    float* dst = g_partial + ((size_t)b * 64 + wb) * 128;
    const float4 r = (h == 0) ? make_float4(a0, a1, a2, a3)
                              : make_float4(b0, b1, b2, b3);
    stcs4(reinterpret_cast<float4*>(dst) + h * 16 + t, r);  // [bank0|bank1]

    // --- last-CTA-per-batch reduction (8 CTAs per batch) ---
    __shared__ int s_last;
    __threadfence();
    __syncthreads();
    if (threadIdx.x == 0) {
        const int v = atomicAdd(&g_ticket[b], 1);
        s_last = (v == 7) ? 1 : 0;
    }
    __syncthreads();
    if (!s_last) return;
    __threadfence();

    const float* __restrict__ prt = g_partial + (size_t)b * 8192;  // 64 x 128
    const int col  = threadIdx.x & 127;
    const int half = threadIdx.x >> 7;
    float s = 0.f;
#pragma unroll
    for (int r2 = 0; r2 < 32; ++r2)
        s += prt[(half * 32 + r2) * 128 + col];
    __shared__ float sb[256];
    sb[half * 128 + col] = s;
    __syncthreads();
    if (threadIdx.x < 64) {
        const int q = threadIdx.x;
        const int qp = (int)PHI((unsigned)q);
        const float s0 = sb[q] + sb[128 + q];
        const float s1v = sb[64 + qp] + sb[192 + qp];
        out[b * 64 + q] = (s0 + s1v) * (1.0f / 4096.0f);
    }
}

extern "C" void kernel_launch(void* const* d_in, const int* in_sizes, int n_in,
                              void* d_out, int out_size) {
    const float* x;
    const int* syn;
    if (in_sizes[0] >= in_sizes[1]) {
        x = (const float*)d_in[0];
        syn = (const int*)d_in[1];
    } else {
        x = (const float*)d_in[1];
        syn = (const int*)d_in[0];
    }
    int B;
    {
        int xs = (in_sizes[0] >= in_sizes[1]) ? in_sizes[0] : in_sizes[1];
        B = xs / (4096 * 64);
        if (B > MAXB) B = MAXB;
    }

    setup_kernel<<<B, 1024>>>(syn);

    // PDL: pool CTAs start while setup drains; prefetch + words 0-3 are
    // code-independent, so only the code-addressed bulk waits on setup.
    cudaLaunchConfig_t cfg = {};
    cfg.gridDim  = dim3((unsigned)(B * 8));
    cfg.blockDim = dim3(256);
    cfg.dynamicSmemBytes = 0;
    cfg.stream = 0;
    cudaLaunchAttribute attrs[1];
    attrs[0].id = cudaLaunchAttributeProgrammaticStreamSerialization;
    attrs[0].val.programmaticStreamSerializationAllowed = 1;
    cfg.attrs = attrs;
    cfg.numAttrs = 1;
    cudaLaunchKernelEx(&cfg, pool_kernel, x, (float*)d_out);
}